// round 9
// baseline (speedup 1.0000x reference)
#include <cuda_runtime.h>
#include <cuda_bf16.h>

// FM_12060268167845: factorization machine forward.
//   d_in[0] idx  i32 [B,K], d_in[1] x f32 [B,K], d_in[2] b f32 [B,K],
//   d_in[3] w f32 [1M,1], d_in[4] V f32 [1M,128], d_in[5] bias f32 [1]
// out f32 [B] = sigmoid(bias + Xw + 0.5/sum(x) * sum_f((XV)^2 - X2V2))
//
// v8: single-launch L2 temporal blocking. Each warp owns 2 batch rows and
// bin-sorts each row's 200 (offset,x) pairs into 8 id-range bins (64MB V
// slices) via two warp-ballot sweeps. Grid = 1024 CTAs = ONE wave; the
// mainloop iterates bins outermost (rows inner), so all SMs gather from
// the same ~51MB-unique slice at any instant -> V-row reuse (~2x) hits L2
// instead of DRAM. Gather loop keeps the proven v3 shape: lane owns 4
// factors, warp-wide 512B LDG.128 bursts, U=8 front-batched.

#define FM_B 8192
#define FM_K 200
#define FM_F 128
#define ROWS_PER_WARP 2
#define WARPS 4
#define THREADS (WARPS * 32)
#define U 8
#define NBIN 8
#define BIN_SHIFT 26              // 64MB slices of the 512MB V table
#define CHUNKS 7                  // ceil(200/32)

struct __align__(8) OffX { unsigned off; float x; };

__global__ __launch_bounds__(THREADS, 8)
void fm_kernel(const int* __restrict__ idx,
               const float* __restrict__ x_vals,
               const float* __restrict__ b_vals,
               const float* __restrict__ w,
               const float* __restrict__ V,
               const float* __restrict__ bias,
               float* __restrict__ out)
{
    const int warp = threadIdx.x >> 5;
    const int lane = threadIdx.x & 31;
    const unsigned lt_mask = (1u << lane) - 1u;

    __shared__ OffX s_pairs[WARPS][ROWS_PER_WARP][FM_K];
    __shared__ int  s_start[WARPS][ROWS_PER_WARP][NBIN + 1];

    const char* __restrict__ Vb = (const char*)V;
    const unsigned lane_off = (unsigned)lane << 4;

    float xw[ROWS_PER_WARP], sx[ROWS_PER_WARP];

    // ---- per-row: stage in registers, ballot bin-sort into shared ----
    #pragma unroll
    for (int r = 0; r < ROWS_PER_WARP; ++r) {
        const int b    = (blockIdx.x * WARPS + warp) * ROWS_PER_WARP + r;
        const int base = b * FM_K;

        OffX e[CHUNKS];
        float xwr = 0.0f, sxr = 0.0f;
        #pragma unroll
        for (int c = 0; c < CHUNKS; ++c) {
            int k = c * 32 + lane;
            if (k < FM_K) {
                int   id = idx[base + k];
                float xv = x_vals[base + k];
                e[c].off = (unsigned)id * (FM_F * 4u);
                e[c].x   = xv;
                sxr += xv;
                xwr = fmaf(b_vals[base + k], __ldg(&w[id]), xwr);
            } else {
                e[c].off = 0xFFFFFFFFu;   // sentinel -> bin 63, never matched
                e[c].x   = 0.0f;
            }
        }
        xw[r] = xwr; sx[r] = sxr;

        // sweep 1: bin counts
        int cnt[NBIN];
        #pragma unroll
        for (int bb = 0; bb < NBIN; ++bb) cnt[bb] = 0;
        #pragma unroll
        for (int c = 0; c < CHUNKS; ++c) {
            unsigned bin = e[c].off >> BIN_SHIFT;
            #pragma unroll
            for (int bb = 0; bb < NBIN; ++bb)
                cnt[bb] += __popc(__ballot_sync(0xffffffffu, bin == (unsigned)bb));
        }
        int run[NBIN];
        int acc = 0;
        #pragma unroll
        for (int bb = 0; bb < NBIN; ++bb) { run[bb] = acc; acc += cnt[bb]; }
        if (lane < NBIN) s_start[warp][r][lane] = run[lane];
        if (lane == 0)   s_start[warp][r][NBIN] = acc;   // == FM_K

        // sweep 2: compact-scatter into bin order
        #pragma unroll
        for (int c = 0; c < CHUNKS; ++c) {
            unsigned bin = e[c].off >> BIN_SHIFT;
            #pragma unroll
            for (int bb = 0; bb < NBIN; ++bb) {
                unsigned msk = __ballot_sync(0xffffffffu, bin == (unsigned)bb);
                if (bin == (unsigned)bb)
                    s_pairs[warp][r][run[bb] + __popc(msk & lt_mask)] = e[c];
                run[bb] += __popc(msk);
            }
        }
    }
    __syncwarp();

    // ---- mainloop: bins outermost so all CTAs hit one V slice at a time ----
    float4 a1[ROWS_PER_WARP];
    float  a2s[ROWS_PER_WARP];
    #pragma unroll
    for (int r = 0; r < ROWS_PER_WARP; ++r) {
        a1[r]  = make_float4(0.f, 0.f, 0.f, 0.f);
        a2s[r] = 0.0f;
    }

    for (int bin = 0; bin < NBIN; ++bin) {
        #pragma unroll
        for (int r = 0; r < ROWS_PER_WARP; ++r) {
            const OffX* __restrict__ sp = s_pairs[warp][r];
            const int lo = s_start[warp][r][bin];
            const int hi = s_start[warp][r][bin + 1];
            for (int k0 = lo; k0 < hi; k0 += U) {
                const int n = hi - k0;           // >=1; may be < U at tail
                float4 v[U];
                float  xr[U];
                #pragma unroll
                for (int u = 0; u < U; ++u) {
                    if (u < n) {
                        OffX ee = sp[k0 + u];
                        xr[u] = ee.x;
                        v[u]  = __ldg((const float4*)(Vb + ee.off + lane_off));
                    }
                }
                #pragma unroll
                for (int u = 0; u < U; ++u) {
                    if (u < n) {
                        float x  = xr[u];
                        float x2 = x * x;
                        a1[r].x = fmaf(x, v[u].x, a1[r].x);
                        a1[r].y = fmaf(x, v[u].y, a1[r].y);
                        a1[r].z = fmaf(x, v[u].z, a1[r].z);
                        a1[r].w = fmaf(x, v[u].w, a1[r].w);
                        float n2 = fmaf(v[u].x, v[u].x,
                                   fmaf(v[u].y, v[u].y,
                                   fmaf(v[u].z, v[u].z, v[u].w * v[u].w)));
                        a2s[r] = fmaf(x2, n2, a2s[r]);
                    }
                }
            }
        }
    }

    // ---- reductions + output ----
    #pragma unroll
    for (int r = 0; r < ROWS_PER_WARP; ++r) {
        float pq = fmaf(a1[r].x, a1[r].x,
                   fmaf(a1[r].y, a1[r].y,
                   fmaf(a1[r].z, a1[r].z, a1[r].w * a1[r].w))) - a2s[r];
        float xwr = xw[r];
        float sxr = sx[r];
        #pragma unroll
        for (int o = 16; o > 0; o >>= 1) {
            pq  += __shfl_down_sync(0xffffffffu, pq,  o);
            xwr += __shfl_down_sync(0xffffffffu, xwr, o);
            sxr += __shfl_down_sync(0xffffffffu, sxr, o);
        }
        if (lane == 0) {
            const int b = (blockIdx.x * WARPS + warp) * ROWS_PER_WARP + r;
            float p     = 0.5f * (1.0f / sxr) * pq;
            float logit = bias[0] + xwr + p;
            out[b] = 1.0f / (1.0f + __expf(-logit));
        }
    }
}

extern "C" void kernel_launch(void* const* d_in, const int* in_sizes, int n_in,
                              void* d_out, int out_size)
{
    const int*   idx    = (const int*)d_in[0];
    const float* x_vals = (const float*)d_in[1];
    const float* b_vals = (const float*)d_in[2];
    const float* w      = (const float*)d_in[3];
    const float* V      = (const float*)d_in[4];
    const float* bias   = (const float*)d_in[5];
    float*       out    = (float*)d_out;
    (void)in_sizes; (void)n_in; (void)out_size;

    const int grid = FM_B / (WARPS * ROWS_PER_WARP);   // 1024 = one wave
    fm_kernel<<<grid, THREADS>>>(idx, x_vals, b_vals, w, V, bias, out);
}

// round 10
// speedup vs baseline: 1.4928x; 1.4928x over previous
#include <cuda_runtime.h>
#include <cuda_bf16.h>

// FM_12060268167845: factorization machine forward.
//   d_in[0] idx  i32 [B,K], d_in[1] x f32 [B,K], d_in[2] b f32 [B,K],
//   d_in[3] w f32 [1M,1], d_in[4] V f32 [1M,128], d_in[5] bias f32 [1]
// out f32 [B] = sigmoid(bias + Xw + 0.5/sum(x) * sum_f((XV)^2 - X2V2))
//
// v9 = v3 execution shape + v8 locality, composed:
//   - Each warp ballot-bin-sorts its row's 200 (offset,x) pairs into 8
//     id-range bins (64MB V slices) in shared -- one-time cost.
//   - Mainloop is v3's UNCHANGED dense U=8 front-batched LDG.128 loop over
//     the sorted array: no segmentation, no predication, full MLP.
//   - Because every warp marches its sorted list at the same rate,
//     concurrent gathers cluster into the same V slice -> row reuse (~2x)
//     hits L2 instead of DRAM (v8 measured 471MB vs v3's 731MB).
// 2048 CTAs, 4 warps (1 row each), 8 CTAs/SM -- v3's proven 81%-eff shape.

#define FM_B 8192
#define FM_K 200
#define FM_F 128
#define ROWS_PER_BLOCK 4
#define THREADS (ROWS_PER_BLOCK * 32)
#define U 8                        // FM_K % U == 0
#define NBIN 8
#define BIN_SHIFT 26               // 64MB slices of the 512MB V table
#define CHUNKS 7                   // ceil(200/32)

struct __align__(8) OffX { unsigned off; float x; };

__global__ __launch_bounds__(THREADS, 8)
void fm_kernel(const int* __restrict__ idx,
               const float* __restrict__ x_vals,
               const float* __restrict__ b_vals,
               const float* __restrict__ w,
               const float* __restrict__ V,
               const float* __restrict__ bias,
               float* __restrict__ out)
{
    const int warp = threadIdx.x >> 5;
    const int lane = threadIdx.x & 31;
    const int b    = blockIdx.x * ROWS_PER_BLOCK + warp;
    const unsigned lt_mask = (1u << lane) - 1u;

    __shared__ OffX s_pairs[ROWS_PER_BLOCK][FM_K];

    // ---- stage row in registers; fold linear term + sum(x) ----
    OffX e[CHUNKS];
    float xw = 0.0f, sx = 0.0f;
    const int base = b * FM_K;
    #pragma unroll
    for (int c = 0; c < CHUNKS; ++c) {
        int k = c * 32 + lane;
        if (k < FM_K) {
            int   id = idx[base + k];
            float xv = x_vals[base + k];
            e[c].off = (unsigned)id * (FM_F * 4u);   // id * 512 bytes
            e[c].x   = xv;
            sx += xv;
            xw = fmaf(b_vals[base + k], __ldg(&w[id]), xw);
        } else {
            e[c].off = 0xFFFFFFFFu;                  // bin 63: never scattered
            e[c].x   = 0.0f;
        }
    }

    // ---- ballot bin-sort into shared (bin = top 3 bits of offset) ----
    int cnt[NBIN];
    #pragma unroll
    for (int bb = 0; bb < NBIN; ++bb) cnt[bb] = 0;
    #pragma unroll
    for (int c = 0; c < CHUNKS; ++c) {
        unsigned bin = e[c].off >> BIN_SHIFT;
        #pragma unroll
        for (int bb = 0; bb < NBIN; ++bb)
            cnt[bb] += __popc(__ballot_sync(0xffffffffu, bin == (unsigned)bb));
    }
    int run[NBIN];
    {
        int acc = 0;
        #pragma unroll
        for (int bb = 0; bb < NBIN; ++bb) { run[bb] = acc; acc += cnt[bb]; }
    }
    #pragma unroll
    for (int c = 0; c < CHUNKS; ++c) {
        unsigned bin = e[c].off >> BIN_SHIFT;
        #pragma unroll
        for (int bb = 0; bb < NBIN; ++bb) {
            unsigned msk = __ballot_sync(0xffffffffu, bin == (unsigned)bb);
            if (bin == (unsigned)bb)
                s_pairs[warp][run[bb] + __popc(msk & lt_mask)] = e[c];
            run[bb] += __popc(msk);
        }
    }
    __syncwarp();

    // ---- v3 dense mainloop over the bin-sorted array ----
    const char* __restrict__ Vb = (const char*)V;
    const unsigned lane_off = (unsigned)lane << 4;
    const OffX* __restrict__ sp = s_pairs[warp];

    float4 a1  = make_float4(0.f, 0.f, 0.f, 0.f);
    float  a2s = 0.0f;

    for (int k0 = 0; k0 < FM_K; k0 += U) {
        float4 v[U];
        float  xr[U];
        #pragma unroll
        for (int u = 0; u < U; ++u) {
            OffX ee = sp[k0 + u];
            xr[u] = ee.x;
            v[u]  = __ldg((const float4*)(Vb + ee.off + lane_off));
        }
        #pragma unroll
        for (int u = 0; u < U; ++u) {
            float x  = xr[u];
            float x2 = x * x;
            a1.x = fmaf(x, v[u].x, a1.x);
            a1.y = fmaf(x, v[u].y, a1.y);
            a1.z = fmaf(x, v[u].z, a1.z);
            a1.w = fmaf(x, v[u].w, a1.w);
            float n2 = fmaf(v[u].x, v[u].x,
                       fmaf(v[u].y, v[u].y,
                       fmaf(v[u].z, v[u].z, v[u].w * v[u].w)));
            a2s = fmaf(x2, n2, a2s);
        }
    }

    // ---- reduction + output ----
    float pq = fmaf(a1.x, a1.x,
               fmaf(a1.y, a1.y,
               fmaf(a1.z, a1.z, a1.w * a1.w))) - a2s;

    #pragma unroll
    for (int o = 16; o > 0; o >>= 1) {
        pq += __shfl_down_sync(0xffffffffu, pq, o);
        xw += __shfl_down_sync(0xffffffffu, xw, o);
        sx += __shfl_down_sync(0xffffffffu, sx, o);
    }

    if (lane == 0) {
        float p     = 0.5f * (1.0f / sx) * pq;
        float logit = bias[0] + xw + p;
        out[b] = 1.0f / (1.0f + __expf(-logit));
    }
}

extern "C" void kernel_launch(void* const* d_in, const int* in_sizes, int n_in,
                              void* d_out, int out_size)
{
    const int*   idx    = (const int*)d_in[0];
    const float* x_vals = (const float*)d_in[1];
    const float* b_vals = (const float*)d_in[2];
    const float* w      = (const float*)d_in[3];
    const float* V      = (const float*)d_in[4];
    const float* bias   = (const float*)d_in[5];
    float*       out    = (float*)d_out;
    (void)in_sizes; (void)n_in; (void)out_size;

    fm_kernel<<<FM_B / ROWS_PER_BLOCK, THREADS>>>(idx, x_vals, b_vals, w, V, bias, out);
}

// round 11
// speedup vs baseline: 1.5637x; 1.0475x over previous
#include <cuda_runtime.h>
#include <cuda_bf16.h>

// FM_12060268167845: factorization machine forward.
//   d_in[0] idx  i32 [B,K], d_in[1] x f32 [B,K], d_in[2] b f32 [B,K],
//   d_in[3] w f32 [1M,1], d_in[4] V f32 [1M,128], d_in[5] bias f32 [1]
// out f32 [B] = sigmoid(bias + Xw + 0.5/sum(x) * sum_f((XV)^2 - X2V2))
//
// v10 = v9 (ballot bin-sort + dense v3 mainloop) made single-wave:
// grid = 1024 CTAs (all resident), each warp processes TWO rows
// sequentially (sort+gather row A, then row B). Both row-generations start
// aligned across the whole chip, so every concurrent gather targets the
// same 64MB V slice -> row reuse lands in L2 (v8 measured 471MB total
// DRAM vs v9's 614MB; v9's loss was ragged wave-2 start, removed here).

#define FM_B 8192
#define FM_K 200
#define FM_F 128
#define WARPS 4
#define THREADS (WARPS * 32)
#define ROWS_PER_WARP 2
#define U 8                        // FM_K % U == 0
#define NBIN 8
#define BIN_SHIFT 26               // 64MB slices of the 512MB V table
#define CHUNKS 7                   // ceil(200/32)

struct __align__(8) OffX { unsigned off; float x; };

__global__ __launch_bounds__(THREADS, 8)
void fm_kernel(const int* __restrict__ idx,
               const float* __restrict__ x_vals,
               const float* __restrict__ b_vals,
               const float* __restrict__ w,
               const float* __restrict__ V,
               const float* __restrict__ bias,
               float* __restrict__ out)
{
    const int warp = threadIdx.x >> 5;
    const int lane = threadIdx.x & 31;
    const unsigned lt_mask = (1u << lane) - 1u;

    __shared__ OffX s_pairs[WARPS][FM_K];

    const char* __restrict__ Vb = (const char*)V;
    const unsigned lane_off = (unsigned)lane << 4;

    const int gwarp = blockIdx.x * WARPS + warp;   // 0..4095

    for (int r = 0; r < ROWS_PER_WARP; ++r) {
        const int b    = gwarp * ROWS_PER_WARP + r;
        const int base = b * FM_K;

        // ---- stage row in registers; fold linear term + sum(x) ----
        OffX e[CHUNKS];
        float xw = 0.0f, sx = 0.0f;
        #pragma unroll
        for (int c = 0; c < CHUNKS; ++c) {
            int k = c * 32 + lane;
            if (k < FM_K) {
                int   id = idx[base + k];
                float xv = x_vals[base + k];
                e[c].off = (unsigned)id * (FM_F * 4u);   // id * 512 bytes
                e[c].x   = xv;
                sx += xv;
                xw = fmaf(b_vals[base + k], __ldg(&w[id]), xw);
            } else {
                e[c].off = 0xFFFFFFFFu;                  // sentinel: no bin
                e[c].x   = 0.0f;
            }
        }

        // ---- ballot bin-sort into shared (bin = top 3 offset bits) ----
        int cnt[NBIN];
        #pragma unroll
        for (int bb = 0; bb < NBIN; ++bb) cnt[bb] = 0;
        #pragma unroll
        for (int c = 0; c < CHUNKS; ++c) {
            unsigned bin = e[c].off >> BIN_SHIFT;
            #pragma unroll
            for (int bb = 0; bb < NBIN; ++bb)
                cnt[bb] += __popc(__ballot_sync(0xffffffffu, bin == (unsigned)bb));
        }
        int run[NBIN];
        {
            int acc = 0;
            #pragma unroll
            for (int bb = 0; bb < NBIN; ++bb) { run[bb] = acc; acc += cnt[bb]; }
        }
        #pragma unroll
        for (int c = 0; c < CHUNKS; ++c) {
            unsigned bin = e[c].off >> BIN_SHIFT;
            #pragma unroll
            for (int bb = 0; bb < NBIN; ++bb) {
                unsigned msk = __ballot_sync(0xffffffffu, bin == (unsigned)bb);
                if (bin == (unsigned)bb)
                    s_pairs[warp][run[bb] + __popc(msk & lt_mask)] = e[c];
                run[bb] += __popc(msk);
            }
        }
        __syncwarp();

        // ---- dense U=8 front-batched mainloop over sorted array ----
        const OffX* __restrict__ sp = s_pairs[warp];
        float4 a1  = make_float4(0.f, 0.f, 0.f, 0.f);
        float  a2s = 0.0f;

        for (int k0 = 0; k0 < FM_K; k0 += U) {
            float4 v[U];
            float  xr[U];
            #pragma unroll
            for (int u = 0; u < U; ++u) {
                OffX ee = sp[k0 + u];
                xr[u] = ee.x;
                v[u]  = __ldg((const float4*)(Vb + ee.off + lane_off));
            }
            #pragma unroll
            for (int u = 0; u < U; ++u) {
                float x  = xr[u];
                float x2 = x * x;
                a1.x = fmaf(x, v[u].x, a1.x);
                a1.y = fmaf(x, v[u].y, a1.y);
                a1.z = fmaf(x, v[u].z, a1.z);
                a1.w = fmaf(x, v[u].w, a1.w);
                float n2 = fmaf(v[u].x, v[u].x,
                           fmaf(v[u].y, v[u].y,
                           fmaf(v[u].z, v[u].z, v[u].w * v[u].w)));
                a2s = fmaf(x2, n2, a2s);
            }
        }

        // ---- reduction + output ----
        float pq = fmaf(a1.x, a1.x,
                   fmaf(a1.y, a1.y,
                   fmaf(a1.z, a1.z, a1.w * a1.w))) - a2s;

        #pragma unroll
        for (int o = 16; o > 0; o >>= 1) {
            pq += __shfl_down_sync(0xffffffffu, pq, o);
            xw += __shfl_down_sync(0xffffffffu, xw, o);
            sx += __shfl_down_sync(0xffffffffu, sx, o);
        }

        if (lane == 0) {
            float p     = 0.5f * (1.0f / sx) * pq;
            float logit = bias[0] + xw + p;
            out[b] = 1.0f / (1.0f + __expf(-logit));
        }
        __syncwarp();
    }
}

extern "C" void kernel_launch(void* const* d_in, const int* in_sizes, int n_in,
                              void* d_out, int out_size)
{
    const int*   idx    = (const int*)d_in[0];
    const float* x_vals = (const float*)d_in[1];
    const float* b_vals = (const float*)d_in[2];
    const float* w      = (const float*)d_in[3];
    const float* V      = (const float*)d_in[4];
    const float* bias   = (const float*)d_in[5];
    float*       out    = (float*)d_out;
    (void)in_sizes; (void)n_in; (void)out_size;

    const int grid = FM_B / (WARPS * ROWS_PER_WARP);   // 1024: one wave
    fm_kernel<<<grid, THREADS>>>(idx, x_vals, b_vals, w, V, bias, out);
}